// round 2
// baseline (speedup 1.0000x reference)
#include <cuda_runtime.h>
#include <cstdint>

typedef unsigned long long ull;

// Problem constants
#define N_  16
#define T_  4096
#define I_  256
#define H_  512
#define C_  128     // number of chunks
#define L_  32      // chunk length, C_*L_ == T_

// packed f32x2 FMA: d = a*b + c elementwise on 2 packed fp32 lanes
#define FMA2(d,a,b,c) asm("fma.rn.f32x2 %0, %1, %2, %3;" : "=l"(d) : "l"(a), "l"(b), "l"(c))

__device__ __forceinline__ float2 unpack2(ull v) {
    float2 r;
    asm("mov.b64 {%0,%1}, %2;" : "=f"(r.x), "=f"(r.y) : "l"(v));
    return r;
}
__device__ __forceinline__ ull pack2(float lo, float hi) {
    ull r;
    asm("mov.b64 %0, {%1,%2};" : "=l"(r) : "f"(lo), "f"(hi));
    return r;
}
__device__ __forceinline__ ull cat2(unsigned lo, unsigned hi) {
    return (ull)lo | ((ull)hi << 32);
}

// -------- static device scratch (no allocation allowed) --------
__device__ float g_Wt  [H_*H_];   // S = Whh^T row-major: Wt[a*H+b] = Whh[b*H+a]
__device__ float g_Wp  [H_*H_];   // packed scan weights: Wp[(k4*H+j)*4+r] = Whh[j*H + k4*4+r]
__device__ float g_P0  [H_*H_];   // squaring ping  (S^2k)
__device__ float g_P0T [H_*H_];   // its transpose
__device__ float g_P1  [H_*H_];   // squaring pong
__device__ float g_P1T [H_*H_];
__device__ float g_lend[C_*N_*H_]; // local state at each chunk end
__device__ float g_hb  [C_*N_*H_]; // true hidden at each chunk end

// monotonic grid barrier state (never reset -> deterministic across graph replays)
__device__ unsigned g_cnt = 0;
__device__ unsigned g_rel = 0;

__device__ __forceinline__ void grid_barrier_dev(unsigned total)
{
    __syncthreads();
    if (threadIdx.x == 0) {
        __threadfence();
        unsigned my = atomicAdd(&g_cnt, 1u);
        if ((my % total) == total - 1u) {
            atomicAdd(&g_rel, 1u);
        } else {
            unsigned need = my / total + 1u;
            while (*((volatile unsigned*)&g_rel) < need) { }
        }
    }
    __syncthreads();
}

// -------- K0: build Wt (S row-major) and Wp (packed scan weights) --------
__global__ void k_prep(const float* __restrict__ Whh)
{
    int idx = blockIdx.x * blockDim.x + threadIdx.x;   // over H*H
    if (idx < H_*H_) {
        int j = idx / H_, k = idx % H_;
        float v = Whh[idx];                 // Whh[j][k]
        g_Wt[k*H_ + j] = v;                 // S[k][j]
        g_Wp[((k >> 2)*H_ + j)*4 + (k & 3)] = v;
    }
}

// ---------------------------------------------------------------------------
// gemm2: C[m][n] = sum_k A[m][k] * Bt[n][k]      (A row-major MxK, Bt row-major NxK)
// tile 128m x 64n, BK=32, 256 threads, per-thread 8m x 4n, f32x2 over k-pairs.
// MODE 1: RNN projection epilogue (q shift + bias + initial), C pitch = H_
// MODE 2: plain store + transposed store (for matrix squaring), pitch = H_
// ---------------------------------------------------------------------------
template<int MODE>
__global__ void __launch_bounds__(256, 1)
gemm2(const float* __restrict__ A, const float* __restrict__ Bt,
      float* __restrict__ Cc, float* __restrict__ Ct, int K,
      const float* __restrict__ bias, const float* __restrict__ initial)
{
    __shared__ __align__(16) float As[128][36];
    __shared__ __align__(16) float Bs[64][36];

    const int tid = threadIdx.x;
    const int bm = blockIdx.y * 128;
    const int bn = blockIdx.x * 64;
    const int tx = tid & 15;        // n group: bn + tx*4
    const int ty = tid >> 4;        // m group: bm + ty*8

    // A tile loaders: 128 rows x 32 k ; 2 threads/row, 4 float4 each
    const int arow = tid >> 1;
    const int aoff = (tid & 1) * 16;
    // B tile loaders: 64 rows x 32 k ; 4 threads/row, 2 float4 each
    const int brow = tid >> 2;
    const int boff = (tid & 3) * 8;

    ull acc2[8][4];
#pragma unroll
    for (int i = 0; i < 8; ++i)
#pragma unroll
        for (int jj = 0; jj < 4; ++jj) acc2[i][jj] = 0ull;

    for (int kt = 0; kt < K; kt += 32) {
        const float* Ab = A + (size_t)(bm + arow) * K + kt + aoff;
#pragma unroll
        for (int u = 0; u < 4; ++u)
            *(float4*)&As[arow][aoff + u*4] = *(const float4*)&Ab[u*4];
        const float* Bb = Bt + (size_t)(bn + brow) * K + kt + boff;
#pragma unroll
        for (int u = 0; u < 2; ++u)
            *(float4*)&Bs[brow][boff + u*4] = *(const float4*)&Bb[u*4];
        __syncthreads();

#pragma unroll
        for (int k4 = 0; k4 < 8; ++k4) {
            ulonglong2 av[8], bv[4];
#pragma unroll
            for (int i = 0; i < 8; ++i)
                av[i] = *(const ulonglong2*)&As[ty*8 + i][k4*4];
#pragma unroll
            for (int jj = 0; jj < 4; ++jj)
                bv[jj] = *(const ulonglong2*)&Bs[tx*4 + jj][k4*4];
#pragma unroll
            for (int i = 0; i < 8; ++i)
#pragma unroll
                for (int jj = 0; jj < 4; ++jj) {
                    FMA2(acc2[i][jj], av[i].x, bv[jj].x, acc2[i][jj]);
                    FMA2(acc2[i][jj], av[i].y, bv[jj].y, acc2[i][jj]);
                }
        }
        __syncthreads();
    }

    if (MODE == 2) {
#pragma unroll
        for (int i = 0; i < 8; ++i) {
            int m = bm + ty*8 + i;
            float v[4];
#pragma unroll
            for (int jj = 0; jj < 4; ++jj) {
                float2 f = unpack2(acc2[i][jj]);
                v[jj] = f.x + f.y;
                Ct[(size_t)(bn + tx*4 + jj)*H_ + m] = v[jj];
            }
            *(float4*)&Cc[(size_t)m*H_ + bn + tx*4] = make_float4(v[0],v[1],v[2],v[3]);
        }
    } else {
        float4 bv = *(const float4*)&bias[bn + tx*4];
#pragma unroll
        for (int i = 0; i < 8; ++i) {
            int r = bm + ty*8 + i;
            int s = r & (T_ - 1);
            int n = r >> 12;
            float2 f0 = unpack2(acc2[i][0]);
            float2 f1 = unpack2(acc2[i][1]);
            float2 f2 = unpack2(acc2[i][2]);
            float2 f3 = unpack2(acc2[i][3]);
            float4 v = make_float4(f0.x+f0.y+bv.x, f1.x+f1.y+bv.y,
                                   f2.x+f2.y+bv.z, f3.x+f3.y+bv.w);
            if (s < T_ - 1)
                *(float4*)&Cc[((size_t)n*T_ + s + 1)*H_ + bn + tx*4] = v;
            if (s == 0) {
                float4 iv = *(const float4*)&initial[(size_t)n*H_ + bn + tx*4];
                *(float4*)&Cc[((size_t)n*T_)*H_ + bn + tx*4]
                    = make_float4(v.x+iv.x, v.y+iv.y, v.z+iv.z, v.w+iv.w);
            }
        }
    }
}

// -------- K2: local scan per chunk (carry-in = 0), in place over q --------
__global__ void __launch_bounds__(512, 1)
k_local(const float* __restrict__ Wp, float* __restrict__ q, float* __restrict__ lend)
{
    __shared__ __align__(16) float hs[N_][H_];   // [n][k]
    const int c = blockIdx.x;
    const int j = threadIdx.x;
    const int t0 = c * L_;

#pragma unroll
    for (int n = 0; n < N_; ++n)
        hs[n][j] = q[((size_t)n*T_ + t0)*H_ + j];
    __syncthreads();

    for (int s = 1; s < L_; ++s) {
        const size_t t = (size_t)t0 + s;
        ull acc2[N_];
#pragma unroll
        for (int n = 0; n < N_; ++n)
            acc2[n] = pack2(q[((size_t)n*T_ + t)*H_ + j], 0.f);

#pragma unroll 2
        for (int k4 = 0; k4 < H_/4; ++k4) {
            ulonglong2 w = *(const ulonglong2*)&Wp[((size_t)k4*H_ + j)*4];
#pragma unroll
            for (int n = 0; n < N_; ++n) {
                ulonglong2 h = *(const ulonglong2*)&hs[n][k4*4];
                FMA2(acc2[n], h.x, w.x, acc2[n]);
                FMA2(acc2[n], h.y, w.y, acc2[n]);
            }
        }
        __syncthreads();
#pragma unroll
        for (int n = 0; n < N_; ++n) {
            float2 f = unpack2(acc2[n]);
            float v = f.x + f.y;
            hs[n][j] = v;
            q[((size_t)n*T_ + t)*H_ + j] = v;
        }
        __syncthreads();
    }
#pragma unroll
    for (int n = 0; n < N_; ++n)
        lend[((size_t)c*N_ + n)*H_ + j] = hs[n][j];
}

// -------- K4: boundary scan (persistent, grid barrier) --------
// hb[0] = lend[0];  hb[c][n][j] = sum_k hb[c-1][n][k] * S32T[j][k] + lend[c][n][j]
__global__ void __launch_bounds__(256, 1)
k_bscan(const float* __restrict__ S32T, const float* __restrict__ lend, float* __restrict__ hb)
{
    const int b   = blockIdx.x;            // 0..31
    const int tid = threadIdx.x;
    const unsigned total = gridDim.x;      // 32
    const int n = tid >> 4;                // 0..15
    const int j = b * 16 + (tid & 15);     // 0..511

    {
        int idx = b * 256 + tid;           // 32*256 = 8192 = N*H
        __stcg(&hb[idx], lend[idx]);
    }
    grid_barrier_dev(total);

    const float* wrow = S32T + (size_t)j * H_;   // L1-resident across steps
    for (int c = 1; c < C_; ++c) {
        const float* hrow = hb + (size_t)(c-1)*N_*H_ + (size_t)n*H_;
        ull a0 = 0ull, a1 = 0ull;
#pragma unroll 8
        for (int k4 = 0; k4 < H_/4; ++k4) {
            uint4 hu = __ldcg((const uint4*)&hrow[k4*4]);     // peer-CTA data: L2 path
            ulonglong2 w = *(const ulonglong2*)&wrow[k4*4];
            ull h01 = cat2(hu.x, hu.y);
            ull h23 = cat2(hu.z, hu.w);
            if (k4 & 1) { FMA2(a1, h01, w.x, a1); FMA2(a1, h23, w.y, a1); }
            else        { FMA2(a0, h01, w.x, a0); FMA2(a0, h23, w.y, a0); }
        }
        float2 f0 = unpack2(a0), f1 = unpack2(a1);
        float acc = lend[(size_t)c*N_*H_ + (size_t)n*H_ + j] + ((f0.x+f0.y) + (f1.x+f1.y));
        __stcg(&hb[(size_t)c*N_*H_ + (size_t)n*H_ + j], acc);
        grid_barrier_dev(total);
    }
}

// -------- K5: correction pass per chunk; finalize out0 (+ duplicate to out1) --------
__global__ void __launch_bounds__(512, 1)
k_corr(const float* __restrict__ Wp, const float* __restrict__ hb,
       float* __restrict__ out0, float* __restrict__ out1, int dup)
{
    const int c = blockIdx.x;
    const int j = threadIdx.x;

    if (c == 0) {   // chunk 0: local state IS the answer; just mirror to out1
        if (dup) {
            for (int s = 0; s < L_; ++s) {
#pragma unroll
                for (int n = 0; n < N_; ++n) {
                    size_t idx = ((size_t)n*T_ + s)*H_ + j;
                    out1[idx] = out0[idx];
                }
            }
        }
        return;
    }

    __shared__ __align__(16) float ds[N_][H_];
    const int t0 = c * L_;
#pragma unroll
    for (int n = 0; n < N_; ++n)
        ds[n][j] = hb[((size_t)(c-1)*N_ + n)*H_ + j];
    __syncthreads();

    for (int s = 0; s < L_; ++s) {
        const size_t t = (size_t)t0 + s;
        ull acc2[N_];
#pragma unroll
        for (int n = 0; n < N_; ++n) acc2[n] = 0ull;

#pragma unroll 2
        for (int k4 = 0; k4 < H_/4; ++k4) {
            ulonglong2 w = *(const ulonglong2*)&Wp[((size_t)k4*H_ + j)*4];
#pragma unroll
            for (int n = 0; n < N_; ++n) {
                ulonglong2 h = *(const ulonglong2*)&ds[n][k4*4];
                FMA2(acc2[n], h.x, w.x, acc2[n]);
                FMA2(acc2[n], h.y, w.y, acc2[n]);
            }
        }
        __syncthreads();
#pragma unroll
        for (int n = 0; n < N_; ++n) {
            float2 f = unpack2(acc2[n]);
            float d = f.x + f.y;
            ds[n][j] = d;
            size_t idx = ((size_t)n*T_ + t)*H_ + j;
            float v = out0[idx] + d;
            out0[idx] = v;
            if (dup) out1[idx] = v;
        }
        __syncthreads();
    }
}

// ----------------------------------------------------------------------------
extern "C" void kernel_launch(void* const* d_in, const int* in_sizes, int n_in,
                              void* d_out, int out_size)
{
    const float *x = nullptr, *initial = nullptr, *Wi = nullptr, *bi = nullptr, *Whh = nullptr;
    for (int i = 0; i < n_in; ++i) {
        switch (in_sizes[i]) {
            case N_*T_*I_: x       = (const float*)d_in[i]; break;
            case N_*H_:    initial = (const float*)d_in[i]; break;
            case H_*I_:    Wi      = (const float*)d_in[i]; break;
            case H_:       bi      = (const float*)d_in[i]; break;
            case H_*H_:    Whh     = (const float*)d_in[i]; break;
        }
    }
    if (!x       && n_in > 0) x       = (const float*)d_in[0];
    if (!initial && n_in > 1) initial = (const float*)d_in[1];
    if (!Wi      && n_in > 2) Wi      = (const float*)d_in[2];
    if (!bi      && n_in > 3) bi      = (const float*)d_in[3];
    if (!Whh     && n_in > 4) Whh     = (const float*)d_in[4];

    float* out0 = (float*)d_out;
    const size_t NTH = (size_t)N_ * T_ * H_;
    int dup = ((size_t)out_size >= 2 * NTH) ? 1 : 0;
    float* out1 = out0 + NTH;

    float *Wt, *Wp, *P0, *P0T, *P1, *P1T, *lend, *hb;
    cudaGetSymbolAddress((void**)&Wt,   g_Wt);
    cudaGetSymbolAddress((void**)&Wp,   g_Wp);
    cudaGetSymbolAddress((void**)&P0,   g_P0);
    cudaGetSymbolAddress((void**)&P0T,  g_P0T);
    cudaGetSymbolAddress((void**)&P1,   g_P1);
    cudaGetSymbolAddress((void**)&P1T,  g_P1T);
    cudaGetSymbolAddress((void**)&lend, g_lend);
    cudaGetSymbolAddress((void**)&hb,   g_hb);

    // K0: weight layouts
    k_prep<<<(H_*H_ + 255)/256, 256>>>(Whh);

    // K1: projection q[t] into out0.  proj = x @ Wi^T  (Bt = Wi rows directly)
    {
        dim3 g(H_/64, (N_*T_)/128);
        gemm2<1><<<g, 256>>>(x, Wi, out0, nullptr, I_, bi, initial);
    }

    // K3: S^32 by 5 squarings, keeping (P, P^T) pairs.  S = Whh^T (Wt), S^T = Whh.
    {
        dim3 g(H_/64, H_/128);
        gemm2<2><<<g, 256>>>(Wt, Whh, P0, P0T, H_, nullptr, nullptr);  // S^2
        gemm2<2><<<g, 256>>>(P0, P0T, P1, P1T, H_, nullptr, nullptr);  // S^4
        gemm2<2><<<g, 256>>>(P1, P1T, P0, P0T, H_, nullptr, nullptr);  // S^8
        gemm2<2><<<g, 256>>>(P0, P0T, P1, P1T, H_, nullptr, nullptr);  // S^16
        gemm2<2><<<g, 256>>>(P1, P1T, P0, P0T, H_, nullptr, nullptr);  // S^32
    }

    // K2: local scan (parallel over 128 chunks)
    k_local<<<C_, 512>>>(Wp, out0, lend);

    // K4: boundary scan (persistent kernel, 32 CTAs, grid barrier)
    k_bscan<<<32, 256>>>(P0T, lend, hb);

    // K5: correction + finalize (+ duplicate output)
    k_corr<<<C_, 512>>>(Wp, hb, out0, out1, dup);
}

// round 3
// speedup vs baseline: 1.0923x; 1.0923x over previous
#include <cuda_runtime.h>
#include <cstdint>

typedef unsigned long long ull;

// Problem constants
#define N_  16
#define T_  4096
#define I_  256
#define H_  512
#define C_  128     // number of chunks
#define L_  32      // chunk length, C_*L_ == T_

// packed f32x2 FMA: d = a*b + c elementwise on 2 packed fp32 lanes
#define FMA2(d,a,b,c) asm("fma.rn.f32x2 %0, %1, %2, %3;" : "=l"(d) : "l"(a), "l"(b), "l"(c))

__device__ __forceinline__ float2 unpack2(ull v) {
    float2 r;
    asm("mov.b64 {%0,%1}, %2;" : "=f"(r.x), "=f"(r.y) : "l"(v));
    return r;
}
__device__ __forceinline__ ull pack2(float lo, float hi) {
    ull r;
    asm("mov.b64 %0, {%1,%2};" : "=l"(r) : "f"(lo), "f"(hi));
    return r;
}
__device__ __forceinline__ ull cat2(unsigned lo, unsigned hi) {
    return (ull)lo | ((ull)hi << 32);
}

// -------- static device scratch (no allocation allowed) --------
__device__ float g_Wp  [H_*H_];   // packed scan weights: Wp[(k4*H+j)*4+r] = Whh[j*H + k4*4+r]
__device__ float g_Wit [I_*H_];   // Wi^T : Wit[i*H+j] = Wi[j*I+i]
__device__ float g_P0  [H_*H_];   // squaring ping  (Whh^2k, row-major)
__device__ float g_P1  [H_*H_];   // squaring pong
__device__ float g_lend[C_*N_*H_]; // local state at each chunk end
__device__ float g_hb  [C_*N_*H_]; // true hidden at each chunk end

// monotonic grid barrier state (never reset -> deterministic across graph replays)
__device__ unsigned g_cnt = 0;
__device__ unsigned g_rel = 0;

__device__ __forceinline__ void grid_barrier_dev(unsigned total)
{
    __syncthreads();
    if (threadIdx.x == 0) {
        __threadfence();
        unsigned my = atomicAdd(&g_cnt, 1u);
        if ((my % total) == total - 1u) {
            atomicAdd(&g_rel, 1u);
        } else {
            unsigned need = my / total + 1u;
            while (*((volatile unsigned*)&g_rel) < need) { }
        }
    }
    __syncthreads();
}

// -------- K0: build Wp (packed scan weights) and Wit (Wi transpose) --------
__global__ void k_prep(const float* __restrict__ Whh, const float* __restrict__ Wi)
{
    int idx = blockIdx.x * blockDim.x + threadIdx.x;   // over H*H
    if (idx < H_*H_) {
        int j = idx / H_, k = idx % H_;
        float v = Whh[idx];                 // Whh[j][k]
        g_Wp[((k >> 2)*H_ + j)*4 + (k & 3)] = v;
    }
    if (idx < H_*I_) {
        int j = idx / I_, i = idx % I_;
        g_Wit[i*H_ + j] = Wi[idx];
    }
}

// ---------------------------------------------------------------------------
// gemm_k: C = A[M,K] @ B[K,Nn]   (both row-major, C pitch = Nn)
// tile 128m x 64n, BK=16, 256 threads, per-thread 8m x 4n scalar FFMA.
// MODE 0: plain store (matrix squaring)
// MODE 1: RNN projection epilogue:
//   row r = n*T + s holds proj[n, s]; store q:
//     q[n,0]   = proj[n,0] + bias + initial[n]
//     q[n,s+1] = proj[n,s] + bias          (s <= T-2)
// ---------------------------------------------------------------------------
template<int MODE>
__global__ void __launch_bounds__(256, 2)
gemm_k(const float* __restrict__ A, const float* __restrict__ B,
       float* __restrict__ Cc, int M, int K, int Nn,
       const float* __restrict__ bias, const float* __restrict__ initial)
{
    __shared__ __align__(16) float As[16][136];  // [k][m], row stride 136 (16B aligned)
    __shared__ __align__(16) float Bs[16][64];   // [k][n]

    const int tid = threadIdx.x;
    const int bm = blockIdx.y * 128;
    const int bn = blockIdx.x * 64;
    const int tx = tid & 15;        // n group: bn + tx*4
    const int ty = tid >> 4;        // m group: bm + ty*8

    // A loaders: 128 rows x 16 k, 2 threads per row, 2 float4 each
    const int arow = tid >> 1;
    const int akof = (tid & 1) * 8;
    // B loaders: 16 rows x 64 n, 16 threads per row, 1 float4 each
    const int brow = tid >> 4;
    const int bcol = (tid & 15) * 4;

    float acc[8][4];
#pragma unroll
    for (int i = 0; i < 8; ++i)
#pragma unroll
        for (int jj = 0; jj < 4; ++jj) acc[i][jj] = 0.f;

    for (int kt = 0; kt < K; kt += 16) {
        const float* Ab = A + (size_t)(bm + arow) * K + kt + akof;
        float4 a0 = *(const float4*)&Ab[0];
        float4 a1 = *(const float4*)&Ab[4];
        As[akof+0][arow] = a0.x; As[akof+1][arow] = a0.y;
        As[akof+2][arow] = a0.z; As[akof+3][arow] = a0.w;
        As[akof+4][arow] = a1.x; As[akof+5][arow] = a1.y;
        As[akof+6][arow] = a1.z; As[akof+7][arow] = a1.w;
        *(float4*)&Bs[brow][bcol] = *(const float4*)&B[(size_t)(kt + brow) * Nn + bn + bcol];
        __syncthreads();

#pragma unroll
        for (int k = 0; k < 16; ++k) {
            float4 av0 = *(const float4*)&As[k][ty*8];
            float4 av1 = *(const float4*)&As[k][ty*8 + 4];
            float4 bv  = *(const float4*)&Bs[k][tx*4];
            float am[8] = {av0.x,av0.y,av0.z,av0.w, av1.x,av1.y,av1.z,av1.w};
            float bb[4] = {bv.x,bv.y,bv.z,bv.w};
#pragma unroll
            for (int i = 0; i < 8; ++i)
#pragma unroll
                for (int jj = 0; jj < 4; ++jj)
                    acc[i][jj] = fmaf(am[i], bb[jj], acc[i][jj]);
        }
        __syncthreads();
    }

    if (MODE == 0) {
#pragma unroll
        for (int i = 0; i < 8; ++i) {
            int m = bm + ty*8 + i;
            *(float4*)&Cc[(size_t)m * Nn + bn + tx*4]
                = make_float4(acc[i][0], acc[i][1], acc[i][2], acc[i][3]);
        }
    } else {
        float4 bv = *(const float4*)&bias[bn + tx*4];
#pragma unroll
        for (int i = 0; i < 8; ++i) {
            int r = bm + ty*8 + i;
            int s = r & (T_ - 1);
            int n = r >> 12;
            float4 v = make_float4(acc[i][0]+bv.x, acc[i][1]+bv.y,
                                   acc[i][2]+bv.z, acc[i][3]+bv.w);
            if (s < T_ - 1)
                *(float4*)&Cc[((size_t)n*T_ + s + 1)*H_ + bn + tx*4] = v;
            if (s == 0) {
                float4 iv = *(const float4*)&initial[(size_t)n*H_ + bn + tx*4];
                *(float4*)&Cc[((size_t)n*T_)*H_ + bn + tx*4]
                    = make_float4(v.x+iv.x, v.y+iv.y, v.z+iv.z, v.w+iv.w);
            }
        }
    }
}

// -------- K2: local scan per chunk (carry-in = 0), in place over q --------
__global__ void __launch_bounds__(512, 1)
k_local(const float* __restrict__ Wp, float* __restrict__ q, float* __restrict__ lend)
{
    __shared__ __align__(16) float hs[N_][H_];   // [n][k]
    const int c = blockIdx.x;
    const int j = threadIdx.x;
    const int t0 = c * L_;

#pragma unroll
    for (int n = 0; n < N_; ++n)
        hs[n][j] = q[((size_t)n*T_ + t0)*H_ + j];
    __syncthreads();

    for (int s = 1; s < L_; ++s) {
        const size_t t = (size_t)t0 + s;
        ull acc2[N_];
#pragma unroll
        for (int n = 0; n < N_; ++n)
            acc2[n] = pack2(q[((size_t)n*T_ + t)*H_ + j], 0.f);

#pragma unroll 2
        for (int k4 = 0; k4 < H_/4; ++k4) {
            ulonglong2 w = *(const ulonglong2*)&Wp[((size_t)k4*H_ + j)*4];
#pragma unroll
            for (int n = 0; n < N_; ++n) {
                ulonglong2 h = *(const ulonglong2*)&hs[n][k4*4];
                FMA2(acc2[n], h.x, w.x, acc2[n]);
                FMA2(acc2[n], h.y, w.y, acc2[n]);
            }
        }
        __syncthreads();
#pragma unroll
        for (int n = 0; n < N_; ++n) {
            float2 f = unpack2(acc2[n]);
            float v = f.x + f.y;
            hs[n][j] = v;
            q[((size_t)n*T_ + t)*H_ + j] = v;
        }
        __syncthreads();
    }
#pragma unroll
    for (int n = 0; n < N_; ++n)
        lend[((size_t)c*N_ + n)*H_ + j] = hs[n][j];
}

// -------- K4: boundary scan (persistent, grid barrier) --------
// hb[0] = lend[0];  hb[c][n][j] = sum_k WL[j][k]*hb[c-1][n][k] + lend[c][n][j]
// WL = Whh^L row-major.
__global__ void __launch_bounds__(256, 1)
k_bscan(const float* __restrict__ WL, const float* __restrict__ lend, float* __restrict__ hb)
{
    const int b   = blockIdx.x;            // 0..31
    const int tid = threadIdx.x;
    const unsigned total = gridDim.x;      // 32
    const int n = tid >> 4;                // 0..15
    const int j = b * 16 + (tid & 15);     // 0..511

    {
        int idx = b * 256 + tid;           // 32*256 = 8192 = N*H
        __stcg(&hb[idx], lend[idx]);
    }
    grid_barrier_dev(total);

    const float* wrow = WL + (size_t)j * H_;   // L1-resident across steps
    for (int c = 1; c < C_; ++c) {
        const float* hrow = hb + (size_t)(c-1)*N_*H_ + (size_t)n*H_;
        ull a0 = 0ull, a1 = 0ull;
#pragma unroll 8
        for (int k4 = 0; k4 < H_/4; ++k4) {
            uint4 hu = __ldcg((const uint4*)&hrow[k4*4]);     // peer-CTA data: L2 path
            ulonglong2 w = *(const ulonglong2*)&wrow[k4*4];
            ull h01 = cat2(hu.x, hu.y);
            ull h23 = cat2(hu.z, hu.w);
            if (k4 & 1) { FMA2(a1, h01, w.x, a1); FMA2(a1, h23, w.y, a1); }
            else        { FMA2(a0, h01, w.x, a0); FMA2(a0, h23, w.y, a0); }
        }
        float2 f0 = unpack2(a0), f1 = unpack2(a1);
        float acc = lend[(size_t)c*N_*H_ + (size_t)n*H_ + j] + ((f0.x+f0.y) + (f1.x+f1.y));
        __stcg(&hb[(size_t)c*N_*H_ + (size_t)n*H_ + j], acc);
        grid_barrier_dev(total);
    }
}

// -------- K5: correction pass per chunk; finalize out0 (+ duplicate to out1) --------
__global__ void __launch_bounds__(512, 1)
k_corr(const float* __restrict__ Wp, const float* __restrict__ hb,
       float* __restrict__ out0, float* __restrict__ out1, int dup)
{
    const int c = blockIdx.x;
    const int j = threadIdx.x;

    if (c == 0) {   // chunk 0: local state IS the answer; just mirror to out1
        if (dup) {
            for (int s = 0; s < L_; ++s) {
#pragma unroll
                for (int n = 0; n < N_; ++n) {
                    size_t idx = ((size_t)n*T_ + s)*H_ + j;
                    out1[idx] = out0[idx];
                }
            }
        }
        return;
    }

    __shared__ __align__(16) float ds[N_][H_];
    const int t0 = c * L_;
#pragma unroll
    for (int n = 0; n < N_; ++n)
        ds[n][j] = hb[((size_t)(c-1)*N_ + n)*H_ + j];
    __syncthreads();

    for (int s = 0; s < L_; ++s) {
        const size_t t = (size_t)t0 + s;
        ull acc2[N_];
#pragma unroll
        for (int n = 0; n < N_; ++n) acc2[n] = 0ull;

#pragma unroll 2
        for (int k4 = 0; k4 < H_/4; ++k4) {
            ulonglong2 w = *(const ulonglong2*)&Wp[((size_t)k4*H_ + j)*4];
#pragma unroll
            for (int n = 0; n < N_; ++n) {
                ulonglong2 h = *(const ulonglong2*)&ds[n][k4*4];
                FMA2(acc2[n], h.x, w.x, acc2[n]);
                FMA2(acc2[n], h.y, w.y, acc2[n]);
            }
        }
        __syncthreads();
#pragma unroll
        for (int n = 0; n < N_; ++n) {
            float2 f = unpack2(acc2[n]);
            float d = f.x + f.y;
            ds[n][j] = d;
            size_t idx = ((size_t)n*T_ + t)*H_ + j;
            float v = out0[idx] + d;
            out0[idx] = v;
            if (dup) out1[idx] = v;
        }
        __syncthreads();
    }
}

// ----------------------------------------------------------------------------
extern "C" void kernel_launch(void* const* d_in, const int* in_sizes, int n_in,
                              void* d_out, int out_size)
{
    const float *x = nullptr, *initial = nullptr, *Wi = nullptr, *bi = nullptr, *Whh = nullptr;
    for (int i = 0; i < n_in; ++i) {
        switch (in_sizes[i]) {
            case N_*T_*I_: x       = (const float*)d_in[i]; break;
            case N_*H_:    initial = (const float*)d_in[i]; break;
            case H_*I_:    Wi      = (const float*)d_in[i]; break;
            case H_:       bi      = (const float*)d_in[i]; break;
            case H_*H_:    Whh     = (const float*)d_in[i]; break;
        }
    }
    if (!x       && n_in > 0) x       = (const float*)d_in[0];
    if (!initial && n_in > 1) initial = (const float*)d_in[1];
    if (!Wi      && n_in > 2) Wi      = (const float*)d_in[2];
    if (!bi      && n_in > 3) bi      = (const float*)d_in[3];
    if (!Whh     && n_in > 4) Whh     = (const float*)d_in[4];

    float* out0 = (float*)d_out;
    const size_t NTH = (size_t)N_ * T_ * H_;
    int dup = ((size_t)out_size >= 2 * NTH) ? 1 : 0;
    float* out1 = out0 + NTH;

    float *Wp, *Wit, *P0, *P1, *lend, *hb;
    cudaGetSymbolAddress((void**)&Wp,   g_Wp);
    cudaGetSymbolAddress((void**)&Wit,  g_Wit);
    cudaGetSymbolAddress((void**)&P0,   g_P0);
    cudaGetSymbolAddress((void**)&P1,   g_P1);
    cudaGetSymbolAddress((void**)&lend, g_lend);
    cudaGetSymbolAddress((void**)&hb,   g_hb);

    // K0: weight layouts
    k_prep<<<(H_*H_ + 255)/256, 256>>>(Whh, Wi);

    // K1: projection q into out0:  q = x @ Wit  (+ shift/bias/initial epilogue)
    {
        dim3 g(H_/64, (N_*T_)/128);   // (8, 512)
        gemm_k<1><<<g, 256>>>(x, Wit, out0, N_*T_, I_, H_, bi, initial);
    }

    // K3: Whh^32 by 5 squarings (row-major throughout; no transposes needed)
    {
        dim3 g(H_/64, H_/128);        // (8, 4)
        gemm_k<0><<<g, 256>>>(Whh, Whh, P0, H_, H_, H_, nullptr, nullptr); // ^2
        gemm_k<0><<<g, 256>>>(P0,  P0,  P1, H_, H_, H_, nullptr, nullptr); // ^4
        gemm_k<0><<<g, 256>>>(P1,  P1,  P0, H_, H_, H_, nullptr, nullptr); // ^8
        gemm_k<0><<<g, 256>>>(P0,  P0,  P1, H_, H_, H_, nullptr, nullptr); // ^16
        gemm_k<0><<<g, 256>>>(P1,  P1,  P0, H_, H_, H_, nullptr, nullptr); // ^32
    }

    // K2: local scan (parallel over 128 chunks)
    k_local<<<C_, 512>>>(Wp, out0, lend);

    // K4: boundary scan (persistent kernel, 32 CTAs, grid barrier)
    k_bscan<<<32, 256>>>(P0, lend, hb);

    // K5: correction + finalize (+ duplicate output)
    k_corr<<<C_, 512>>>(Wp, hb, out0, out1, dup);
}